// round 15
// baseline (speedup 1.0000x reference)
#include <cuda_runtime.h>
#include <cuda_bf16.h>
#include <stdint.h>

// Problem constants
#define NN 50000
#define NE 800000
#define NF 256
#define NH 128
#define NC 64
#define NHALF 25088   // 196 * 128; first node-half for the tail pipeline

// ============================ device scratch ============================
__device__ int    g_edges[2 * NE];      // [0..NE) = src, [NE..2NE) = dst
__device__ int    g_counts[NN];
__device__ int    g_off[NN + 1];
__device__ int    g_cursor[NN];
__device__ int2   g_csre[NE];           // packed CSR entry: {src, bits(dinv[src])}
__device__ float  g_dinv[NN];
__device__ float  g_H1[NN * NH];
__device__ __nv_bfloat16 g_A1h[NN * NH], g_A1l[NN * NH];    // post-dropout activation, split
__device__ float  g_H2[NN * NC];
__device__ __nv_bfloat16 g_B1h[NH * NF], g_B1l[NH * NF];    // W1^T split: [N][K]
__device__ __nv_bfloat16 g_B2h[NC * NH], g_B2l[NC * NH];    // W2^T split

// ============================ CSR build ============================
__global__ void zero_counts_kernel() {
    int tid = blockIdx.x * blockDim.x + threadIdx.x;
    if (tid < NN) g_counts[tid] = 0;
}

__global__ void convert_hist_kernel(const void* ein) {
    const unsigned int* e32 = (const unsigned int*)ein;
    bool is64 = true;
#pragma unroll
    for (int i = 0; i < 8; i++) {
        if (e32[2 * i + 1] != 0u) { is64 = false; break; }
    }
    int i = blockIdx.x * blockDim.x + threadIdx.x;
    if (i >= 2 * NE) return;
    int v = is64 ? (int)((const long long*)ein)[i] : ((const int*)ein)[i];
    g_edges[i] = v;
    if (i >= NE) atomicAdd(&g_counts[v], 1);
}

__global__ void scan_kernel() {
    __shared__ int sh[1024];
    const int t = threadIdx.x;
    const int per = (NN + 1023) >> 10;
    int lo = t * per;
    int hi = lo + per; if (hi > NN) hi = NN;
    if (lo > NN) lo = NN;
    int s = 0;
    for (int i = lo; i < hi; i++) s += g_counts[i];
    sh[t] = s;
    __syncthreads();
    for (int off = 1; off < 1024; off <<= 1) {
        int v = (t >= off) ? sh[t - off] : 0;
        __syncthreads();
        sh[t] += v;
        __syncthreads();
    }
    int base = (t > 0) ? sh[t - 1] : 0;
    for (int i = lo; i < hi; i++) {
        g_off[i] = base;
        g_cursor[i] = base;
        base += g_counts[i];
        g_dinv[i] = rsqrtf((float)(g_counts[i] + 1));
    }
    if (t == 1023) g_off[NN] = sh[1023];
}

__global__ void fill_kernel() {
    int e = blockIdx.x * blockDim.x + threadIdx.x;
    if (e >= NE) return;
    int d = g_edges[NE + e];
    int s = g_edges[e];
    int p = atomicAdd(&g_cursor[d], 1);
    g_csre[p] = make_int2(s, __float_as_int(g_dinv[s]));
}

// ============================ weight prep (both layers, one launch) ============================
__global__ void wprep_kernel(const float* __restrict__ W1, const float* __restrict__ W2) {
    int i = blockIdx.x * blockDim.x + threadIdx.x;
    if (i < NH * NF) {
        int n = i / NF, k = i % NF;
        float f = W1[k * NH + n];
        __nv_bfloat16 h = __float2bfloat16_rn(f);
        g_B1h[i] = h;
        g_B1l[i] = __float2bfloat16_rn(f - __bfloat162float(h));
    } else if (i < NH * NF + NC * NH) {
        int t = i - NH * NF;
        int n = t / NH, k = t % NH;
        float f = W2[k * NC + n];
        __nv_bfloat16 h = __float2bfloat16_rn(f);
        g_B2h[t] = h;
        g_B2l[t] = __float2bfloat16_rn(f - __bfloat162float(h));
    }
}

// ============================ mma.sync bf16x3 GEMM ============================
__device__ __forceinline__ void mma_bf16(float* c,
                                         uint32_t a0, uint32_t a1, uint32_t a2, uint32_t a3,
                                         uint32_t b0, uint32_t b1) {
    asm volatile(
        "mma.sync.aligned.m16n8k16.row.col.f32.bf16.bf16.f32 "
        "{%0,%1,%2,%3}, {%4,%5,%6,%7}, {%8,%9}, {%0,%1,%2,%3};"
        : "+f"(c[0]), "+f"(c[1]), "+f"(c[2]), "+f"(c[3])
        : "r"(a0), "r"(a1), "r"(a2), "r"(a3), "r"(b0), "r"(b1));
}

// gemm1: C[M,BN] = A[M,K] @ W[K,BN], fp32 in/out, bf16x3 internally.
template <int BN, int K>
__global__ __launch_bounds__(256) void gemm_mma_kernel(
    const float* __restrict__ A,
    const __nv_bfloat16* __restrict__ Bh, const __nv_bfloat16* __restrict__ Bl,
    float* __restrict__ C, int M)
{
    constexpr int BM = 128, BK = 32;
    constexpr int LDA = 40;
    constexpr int WARPS_M = (BN == 128) ? 2 : 4;
    constexpr int WARPS_N = 8 / WARPS_M;
    constexpr int MT = BM / (WARPS_M * 16);
    constexpr int NT = BN / (WARPS_N * 8);

    __shared__ unsigned short Ah[BM * LDA], Al[BM * LDA];
    __shared__ unsigned short Bsh[BN * LDA], Bsl[BN * LDA];

    const int tid = threadIdx.x;
    const int wid = tid >> 5;
    const int lane = tid & 31;
    const int g = lane >> 2;
    const int tig = lane & 3;
    const int warp_m = wid % WARPS_M;
    const int warp_n = wid / WARPS_M;
    const int wm0 = warp_m * MT * 16;
    const int wn0 = warp_n * NT * 8;
    const int row0 = blockIdx.x * BM;

    float acc[MT][NT][4];
#pragma unroll
    for (int mt = 0; mt < MT; mt++)
#pragma unroll
        for (int nt = 0; nt < NT; nt++)
#pragma unroll
            for (int i = 0; i < 4; i++) acc[mt][nt][i] = 0.f;

    for (int kc = 0; kc < K; kc += BK) {
        __syncthreads();
#pragma unroll
        for (int l = 0; l < (BM * BK) / (256 * 4); l++) {
            int idx = l * 256 + tid;
            int r = idx >> 3;
            int kq = (idx & 7) * 4;
            float4 f = make_float4(0.f, 0.f, 0.f, 0.f);
            if (row0 + r < M) f = *(const float4*)&A[(size_t)(row0 + r) * K + kc + kq];
            __nv_bfloat162 h0 = __float22bfloat162_rn(make_float2(f.x, f.y));
            __nv_bfloat162 h1 = __float22bfloat162_rn(make_float2(f.z, f.w));
            float2 hb0 = __bfloat1622float2(h0);
            float2 hb1 = __bfloat1622float2(h1);
            __nv_bfloat162 l0 = __float22bfloat162_rn(make_float2(f.x - hb0.x, f.y - hb0.y));
            __nv_bfloat162 l1 = __float22bfloat162_rn(make_float2(f.z - hb1.x, f.w - hb1.y));
            *(uint32_t*)&Ah[r * LDA + kq]     = *(uint32_t*)&h0;
            *(uint32_t*)&Ah[r * LDA + kq + 2] = *(uint32_t*)&h1;
            *(uint32_t*)&Al[r * LDA + kq]     = *(uint32_t*)&l0;
            *(uint32_t*)&Al[r * LDA + kq + 2] = *(uint32_t*)&l1;
        }
#pragma unroll
        for (int l = 0; l < (BN * BK) / (256 * 8); l++) {
            int idx = l * 256 + tid;
            int n = idx >> 2;
            int kq = (idx & 3) * 8;
            *(uint4*)&Bsh[n * LDA + kq] = *(const uint4*)&Bh[(size_t)n * K + kc + kq];
            *(uint4*)&Bsl[n * LDA + kq] = *(const uint4*)&Bl[(size_t)n * K + kc + kq];
        }
        __syncthreads();

#pragma unroll
        for (int kk = 0; kk < BK; kk += 16) {
            uint32_t af[MT][4], bfh[NT][2], bfl[NT][2];
#pragma unroll
            for (int mt = 0; mt < MT; mt++) {
                int r0 = wm0 + mt * 16 + g;
                af[mt][0] = *(const uint32_t*)&Ah[r0 * LDA + kk + tig * 2];
                af[mt][1] = *(const uint32_t*)&Ah[(r0 + 8) * LDA + kk + tig * 2];
                af[mt][2] = *(const uint32_t*)&Ah[r0 * LDA + kk + 8 + tig * 2];
                af[mt][3] = *(const uint32_t*)&Ah[(r0 + 8) * LDA + kk + 8 + tig * 2];
            }
#pragma unroll
            for (int nt = 0; nt < NT; nt++) {
                int n0 = wn0 + nt * 8 + g;
                bfh[nt][0] = *(const uint32_t*)&Bsh[n0 * LDA + kk + tig * 2];
                bfh[nt][1] = *(const uint32_t*)&Bsh[n0 * LDA + kk + 8 + tig * 2];
                bfl[nt][0] = *(const uint32_t*)&Bsl[n0 * LDA + kk + tig * 2];
                bfl[nt][1] = *(const uint32_t*)&Bsl[n0 * LDA + kk + 8 + tig * 2];
            }
#pragma unroll
            for (int mt = 0; mt < MT; mt++)
#pragma unroll
                for (int nt = 0; nt < NT; nt++) {
                    mma_bf16(acc[mt][nt], af[mt][0], af[mt][1], af[mt][2], af[mt][3],
                             bfh[nt][0], bfh[nt][1]);
                    mma_bf16(acc[mt][nt], af[mt][0], af[mt][1], af[mt][2], af[mt][3],
                             bfl[nt][0], bfl[nt][1]);
                }
#pragma unroll
            for (int mt = 0; mt < MT; mt++) {
                int r0 = wm0 + mt * 16 + g;
                af[mt][0] = *(const uint32_t*)&Al[r0 * LDA + kk + tig * 2];
                af[mt][1] = *(const uint32_t*)&Al[(r0 + 8) * LDA + kk + tig * 2];
                af[mt][2] = *(const uint32_t*)&Al[r0 * LDA + kk + 8 + tig * 2];
                af[mt][3] = *(const uint32_t*)&Al[(r0 + 8) * LDA + kk + 8 + tig * 2];
            }
#pragma unroll
            for (int mt = 0; mt < MT; mt++)
#pragma unroll
                for (int nt = 0; nt < NT; nt++)
                    mma_bf16(acc[mt][nt], af[mt][0], af[mt][1], af[mt][2], af[mt][3],
                             bfh[nt][0], bfh[nt][1]);
        }
    }

#pragma unroll
    for (int mt = 0; mt < MT; mt++) {
        int r0 = row0 + wm0 + mt * 16 + g;
#pragma unroll
        for (int nt = 0; nt < NT; nt++) {
            int c0 = wn0 + nt * 8 + tig * 2;
            if (r0 < M)
                *(float2*)&C[(size_t)r0 * BN + c0] = make_float2(acc[mt][nt][0], acc[mt][nt][1]);
            if (r0 + 8 < M)
                *(float2*)&C[(size_t)(r0 + 8) * BN + c0] = make_float2(acc[mt][nt][2], acc[mt][nt][3]);
        }
    }
}

// gemm2: pre-split bf16 A (from gather128), fp32 out. Processes rows [0, M) of given pointers.
__global__ __launch_bounds__(256) void gemm2_mma_kernel(
    const __nv_bfloat16* __restrict__ A1h, const __nv_bfloat16* __restrict__ A1l,
    const __nv_bfloat16* __restrict__ Bh, const __nv_bfloat16* __restrict__ Bl,
    float* __restrict__ C, int M)
{
    constexpr int BN = 64, K = 128;
    constexpr int BM = 128, BK = 32;
    constexpr int LDA = 40;
    constexpr int WARPS_M = 4, WARPS_N = 2;
    constexpr int MT = BM / (WARPS_M * 16);   // 2
    constexpr int NT = BN / (WARPS_N * 8);    // 4

    __shared__ unsigned short Ah[BM * LDA], Al[BM * LDA];
    __shared__ unsigned short Bsh[BN * LDA], Bsl[BN * LDA];

    const int tid = threadIdx.x;
    const int wid = tid >> 5;
    const int lane = tid & 31;
    const int g = lane >> 2;
    const int tig = lane & 3;
    const int warp_m = wid % WARPS_M;
    const int warp_n = wid / WARPS_M;
    const int wm0 = warp_m * MT * 16;
    const int wn0 = warp_n * NT * 8;
    const int row0 = blockIdx.x * BM;

    float acc[MT][NT][4];
#pragma unroll
    for (int mt = 0; mt < MT; mt++)
#pragma unroll
        for (int nt = 0; nt < NT; nt++)
#pragma unroll
            for (int i = 0; i < 4; i++) acc[mt][nt][i] = 0.f;

    for (int kc = 0; kc < K; kc += BK) {
        __syncthreads();
#pragma unroll
        for (int l = 0; l < (BM * BK) / (256 * 8); l++) {
            int idx = l * 256 + tid;
            int r = idx >> 2;
            int kq = (idx & 3) * 8;
            uint4 vh = make_uint4(0u, 0u, 0u, 0u), vl = make_uint4(0u, 0u, 0u, 0u);
            if (row0 + r < M) {
                vh = *(const uint4*)&A1h[(size_t)(row0 + r) * K + kc + kq];
                vl = *(const uint4*)&A1l[(size_t)(row0 + r) * K + kc + kq];
            }
            *(uint4*)&Ah[r * LDA + kq] = vh;
            *(uint4*)&Al[r * LDA + kq] = vl;
        }
        {
            int n = tid >> 2;
            int kq = (tid & 3) * 8;
            *(uint4*)&Bsh[n * LDA + kq] = *(const uint4*)&Bh[(size_t)n * K + kc + kq];
            *(uint4*)&Bsl[n * LDA + kq] = *(const uint4*)&Bl[(size_t)n * K + kc + kq];
        }
        __syncthreads();

#pragma unroll
        for (int kk = 0; kk < BK; kk += 16) {
            uint32_t af[MT][4], bfh[NT][2], bfl[NT][2];
#pragma unroll
            for (int mt = 0; mt < MT; mt++) {
                int r0 = wm0 + mt * 16 + g;
                af[mt][0] = *(const uint32_t*)&Ah[r0 * LDA + kk + tig * 2];
                af[mt][1] = *(const uint32_t*)&Ah[(r0 + 8) * LDA + kk + tig * 2];
                af[mt][2] = *(const uint32_t*)&Ah[r0 * LDA + kk + 8 + tig * 2];
                af[mt][3] = *(const uint32_t*)&Ah[(r0 + 8) * LDA + kk + 8 + tig * 2];
            }
#pragma unroll
            for (int nt = 0; nt < NT; nt++) {
                int n0 = wn0 + nt * 8 + g;
                bfh[nt][0] = *(const uint32_t*)&Bsh[n0 * LDA + kk + tig * 2];
                bfh[nt][1] = *(const uint32_t*)&Bsh[n0 * LDA + kk + 8 + tig * 2];
                bfl[nt][0] = *(const uint32_t*)&Bsl[n0 * LDA + kk + tig * 2];
                bfl[nt][1] = *(const uint32_t*)&Bsl[n0 * LDA + kk + 8 + tig * 2];
            }
#pragma unroll
            for (int mt = 0; mt < MT; mt++)
#pragma unroll
                for (int nt = 0; nt < NT; nt++) {
                    mma_bf16(acc[mt][nt], af[mt][0], af[mt][1], af[mt][2], af[mt][3],
                             bfh[nt][0], bfh[nt][1]);
                    mma_bf16(acc[mt][nt], af[mt][0], af[mt][1], af[mt][2], af[mt][3],
                             bfl[nt][0], bfl[nt][1]);
                }
#pragma unroll
            for (int mt = 0; mt < MT; mt++) {
                int r0 = wm0 + mt * 16 + g;
                af[mt][0] = *(const uint32_t*)&Al[r0 * LDA + kk + tig * 2];
                af[mt][1] = *(const uint32_t*)&Al[(r0 + 8) * LDA + kk + tig * 2];
                af[mt][2] = *(const uint32_t*)&Al[r0 * LDA + kk + 8 + tig * 2];
                af[mt][3] = *(const uint32_t*)&Al[(r0 + 8) * LDA + kk + 8 + tig * 2];
            }
#pragma unroll
            for (int mt = 0; mt < MT; mt++)
#pragma unroll
                for (int nt = 0; nt < NT; nt++)
                    mma_bf16(acc[mt][nt], af[mt][0], af[mt][1], af[mt][2], af[mt][3],
                             bfh[nt][0], bfh[nt][1]);
        }
    }

#pragma unroll
    for (int mt = 0; mt < MT; mt++) {
        int r0 = row0 + wm0 + mt * 16 + g;
#pragma unroll
        for (int nt = 0; nt < NT; nt++) {
            int c0 = wn0 + nt * 8 + tig * 2;
            if (r0 < M)
                *(float2*)&C[(size_t)r0 * BN + c0] = make_float2(acc[mt][nt][0], acc[mt][nt][1]);
            if (r0 + 8 < M)
                *(float2*)&C[(size_t)(r0 + 8) * BN + c0] = make_float2(acc[mt][nt][2], acc[mt][nt][3]);
        }
    }
}

// ============================ Threefry + dropout ============================
__device__ __forceinline__ unsigned int rotl32(unsigned int x, int d) {
    return (x << d) | (x >> (32 - d));
}
__device__ __forceinline__ void threefry2x32(unsigned int k0, unsigned int k1,
                                             unsigned int x0, unsigned int x1,
                                             unsigned int& o0, unsigned int& o1) {
    unsigned int ks0 = k0, ks1 = k1, ks2 = k0 ^ k1 ^ 0x1BD11BDAu;
    x0 += ks0; x1 += ks1;
#define TF_R4(a, b, c, d)                                 \
    x0 += x1; x1 = rotl32(x1, a); x1 ^= x0;               \
    x0 += x1; x1 = rotl32(x1, b); x1 ^= x0;               \
    x0 += x1; x1 = rotl32(x1, c); x1 ^= x0;               \
    x0 += x1; x1 = rotl32(x1, d); x1 ^= x0;
    TF_R4(13, 15, 26, 6);  x0 += ks1; x1 += ks2 + 1u;
    TF_R4(17, 29, 16, 24); x0 += ks2; x1 += ks0 + 2u;
    TF_R4(13, 15, 26, 6);  x0 += ks0; x1 += ks1 + 3u;
    TF_R4(17, 29, 16, 24); x0 += ks1; x1 += ks2 + 4u;
    TF_R4(13, 15, 26, 6);  x0 += ks2; x1 += ks0 + 5u;
#undef TF_R4
    o0 = x0; o1 = x1;
}
// keep[j]: bit31(b1^b2)==0 for threefry2x32((0,42),(0,j)) — JAX partitionable 32-bit.
__device__ __forceinline__ bool drop_keep(unsigned int j) {
    unsigned int o0, o1;
    threefry2x32(0u, 42u, 0u, j, o0, o1);
    return ((o0 ^ o1) & 0x80000000u) == 0u;
}

// ============================ gathers ============================
// Layer 1 over node range [lo, hi): aggregate fp32 H1, + b1, relu, dropout;
// write split bf16 hi/lo for gemm2. Unroll-4 (register-lean; occupancy matters here).
__global__ void gather128_fused_kernel(const float* __restrict__ H,
                                       const float* __restrict__ b,
                                       int lo, int hi) {
    int gwarp = (blockIdx.x * blockDim.x + threadIdx.x) >> 5;
    int lane = threadIdx.x & 31;
    int nwarp = (gridDim.x * blockDim.x) >> 5;
    const float4* __restrict__ H4 = (const float4*)H;
    float4 bv = ((const float4*)b)[lane];
    for (int d = lo + gwarp; d < hi; d += nwarp) {
        float dd = g_dinv[d];
        float4 hv = H4[(size_t)d * 32 + lane];
        float4 acc = make_float4(dd * hv.x, dd * hv.y, dd * hv.z, dd * hv.w);
        int i = g_off[d], e1 = g_off[d + 1];
        for (; i + 4 <= e1; i += 4) {
            int2 p0 = g_csre[i], p1 = g_csre[i + 1], p2 = g_csre[i + 2], p3 = g_csre[i + 3];
            float4 v0 = H4[(size_t)p0.x * 32 + lane];
            float4 v1 = H4[(size_t)p1.x * 32 + lane];
            float4 v2 = H4[(size_t)p2.x * 32 + lane];
            float4 v3 = H4[(size_t)p3.x * 32 + lane];
            float w0 = __int_as_float(p0.y), w1 = __int_as_float(p1.y);
            float w2 = __int_as_float(p2.y), w3 = __int_as_float(p3.y);
            acc.x += w0 * v0.x + w1 * v1.x + w2 * v2.x + w3 * v3.x;
            acc.y += w0 * v0.y + w1 * v1.y + w2 * v2.y + w3 * v3.y;
            acc.z += w0 * v0.z + w1 * v1.z + w2 * v2.z + w3 * v3.z;
            acc.w += w0 * v0.w + w1 * v1.w + w2 * v2.w + w3 * v3.w;
        }
        for (; i < e1; i++) {
            int2 p = g_csre[i];
            float w = __int_as_float(p.y);
            float4 v = H4[(size_t)p.x * 32 + lane];
            acc.x += w * v.x; acc.y += w * v.y; acc.z += w * v.z; acc.w += w * v.w;
        }
        unsigned int j = (unsigned int)d * 128u + (unsigned int)lane * 4u;
        acc.x = fmaxf(fmaf(dd, acc.x, bv.x), 0.f);
        acc.y = fmaxf(fmaf(dd, acc.y, bv.y), 0.f);
        acc.z = fmaxf(fmaf(dd, acc.z, bv.z), 0.f);
        acc.w = fmaxf(fmaf(dd, acc.w, bv.w), 0.f);
        acc.x = drop_keep(j + 0u) ? 2.f * acc.x : 0.f;
        acc.y = drop_keep(j + 1u) ? 2.f * acc.y : 0.f;
        acc.z = drop_keep(j + 2u) ? 2.f * acc.z : 0.f;
        acc.w = drop_keep(j + 3u) ? 2.f * acc.w : 0.f;
        __nv_bfloat162 h0 = __float22bfloat162_rn(make_float2(acc.x, acc.y));
        __nv_bfloat162 h1 = __float22bfloat162_rn(make_float2(acc.z, acc.w));
        float2 hb0 = __bfloat1622float2(h0);
        float2 hb1 = __bfloat1622float2(h1);
        __nv_bfloat162 l0 = __float22bfloat162_rn(make_float2(acc.x - hb0.x, acc.y - hb0.y));
        __nv_bfloat162 l1 = __float22bfloat162_rn(make_float2(acc.z - hb1.x, acc.w - hb1.y));
        uint2 hw = make_uint2(*(uint32_t*)&h0, *(uint32_t*)&h1);
        uint2 lw = make_uint2(*(uint32_t*)&l0, *(uint32_t*)&l1);
        *(uint2*)&g_A1h[(size_t)d * 128 + lane * 4] = hw;
        *(uint2*)&g_A1l[(size_t)d * 128 + lane * 4] = lw;
    }
}

// Layer 2: aggregate fp32 H2 + b2 -> fp32 d_out.
__global__ void gather64_kernel(const float* __restrict__ H, const float* __restrict__ b,
                                float* __restrict__ out) {
    int gwarp = (blockIdx.x * blockDim.x + threadIdx.x) >> 5;
    int lane = threadIdx.x & 31;
    int nwarp = (gridDim.x * blockDim.x) >> 5;
    const float2* __restrict__ H2 = (const float2*)H;
    float2 bv = ((const float2*)b)[lane];
    for (int d = gwarp; d < NN; d += nwarp) {
        float dd = g_dinv[d];
        float2 hv = H2[(size_t)d * 32 + lane];
        float2 acc = make_float2(dd * hv.x, dd * hv.y);
        int i = g_off[d], e1 = g_off[d + 1];
        for (; i + 4 <= e1; i += 4) {
            int2 p0 = g_csre[i], p1 = g_csre[i + 1], p2 = g_csre[i + 2], p3 = g_csre[i + 3];
            float2 v0 = H2[(size_t)p0.x * 32 + lane];
            float2 v1 = H2[(size_t)p1.x * 32 + lane];
            float2 v2 = H2[(size_t)p2.x * 32 + lane];
            float2 v3 = H2[(size_t)p3.x * 32 + lane];
            float w0 = __int_as_float(p0.y), w1 = __int_as_float(p1.y);
            float w2 = __int_as_float(p2.y), w3 = __int_as_float(p3.y);
            acc.x += w0 * v0.x + w1 * v1.x + w2 * v2.x + w3 * v3.x;
            acc.y += w0 * v0.y + w1 * v1.y + w2 * v2.y + w3 * v3.y;
        }
        for (; i < e1; i++) {
            int2 p = g_csre[i];
            float w = __int_as_float(p.y);
            float2 v = H2[(size_t)p.x * 32 + lane];
            acc.x += w * v.x; acc.y += w * v.y;
        }
        acc.x = fmaf(dd, acc.x, bv.x);
        acc.y = fmaf(dd, acc.y, bv.y);
        ((float2*)out)[(size_t)d * 32 + lane] = acc;
    }
}

// ============================ launch ============================
extern "C" void kernel_launch(void* const* d_in, const int* in_sizes, int n_in,
                              void* d_out, int out_size) {
    static cudaStream_t s2 = 0;
    static cudaEvent_t ev_fork = 0, ev_join = 0, ev_g0 = 0, ev_gm = 0;
    if (!s2) {
        cudaStreamCreateWithFlags(&s2, cudaStreamNonBlocking);
        cudaEventCreateWithFlags(&ev_fork, cudaEventDisableTiming);
        cudaEventCreateWithFlags(&ev_join, cudaEventDisableTiming);
        cudaEventCreateWithFlags(&ev_g0, cudaEventDisableTiming);
        cudaEventCreateWithFlags(&ev_gm, cudaEventDisableTiming);
    }

    const float* x  = 0; const void* ei = 0;
    const float* W1 = 0; const float* b1 = 0;
    const float* W2 = 0; const float* b2 = 0;
    for (int i = 0; i < n_in; i++) {
        switch (in_sizes[i]) {
            case NN * NF:  x  = (const float*)d_in[i]; break;
            case 2 * NE:   ei = d_in[i];               break;
            case NF * NH:  W1 = (const float*)d_in[i]; break;
            case NH:       b1 = (const float*)d_in[i]; break;
            case NH * NC:  W2 = (const float*)d_in[i]; break;
            case NC:       b2 = (const float*)d_in[i]; break;
        }
    }
    float* out = (float*)d_out;

    float* H1; cudaGetSymbolAddress((void**)&H1, g_H1);
    float* H2; cudaGetSymbolAddress((void**)&H2, g_H2);
    __nv_bfloat16 *B1h, *B1l, *B2h, *B2l, *A1h, *A1l;
    cudaGetSymbolAddress((void**)&B1h, g_B1h);
    cudaGetSymbolAddress((void**)&B1l, g_B1l);
    cudaGetSymbolAddress((void**)&B2h, g_B2h);
    cudaGetSymbolAddress((void**)&B2l, g_B2l);
    cudaGetSymbolAddress((void**)&A1h, g_A1h);
    cudaGetSymbolAddress((void**)&A1l, g_A1l);

    // Fork: CSR build on s2; weight prep + GEMM1 on main.
    cudaEventRecord(ev_fork, 0);
    cudaStreamWaitEvent(s2, ev_fork, 0);

    zero_counts_kernel<<<(NN + 255) / 256, 256, 0, s2>>>();
    convert_hist_kernel<<<(2 * NE + 255) / 256, 256, 0, s2>>>(ei);
    scan_kernel<<<1, 1024, 0, s2>>>();
    fill_kernel<<<(NE + 255) / 256, 256, 0, s2>>>();
    cudaEventRecord(ev_join, s2);

    wprep_kernel<<<(NH * NF + NC * NH + 255) / 256, 256>>>(W1, W2);
    gemm_mma_kernel<NH, NF><<<(NN + 127) / 128, 256>>>(x, B1h, B1l, H1, NN);

    cudaStreamWaitEvent(0, ev_join, 0);

    // Tail pipeline: gather128(half0) -> { gemm2(half0) on s2  ||  gather128(half1) on main }
    //                -> gemm2(half1) on main -> join -> gather64.
    gather128_fused_kernel<<<2048, 256>>>(H1, b1, 0, NHALF);
    cudaEventRecord(ev_g0, 0);
    cudaStreamWaitEvent(s2, ev_g0, 0);
    gemm2_mma_kernel<<<NHALF / 128, 256, 0, s2>>>(A1h, A1l, B2h, B2l, H2, NHALF);
    cudaEventRecord(ev_gm, s2);

    gather128_fused_kernel<<<2048, 256>>>(H1, b1, NHALF, NN);
    gemm2_mma_kernel<<<(NN - NHALF + 127) / 128, 256>>>(
        A1h + (size_t)NHALF * NH, A1l + (size_t)NHALF * NH, B2h, B2l,
        H2 + (size_t)NHALF * NC, NN - NHALF);
    cudaStreamWaitEvent(0, ev_gm, 0);

    gather64_kernel<<<1024, 256>>>(H2, b2, out);
}

// round 16
// speedup vs baseline: 1.1088x; 1.1088x over previous
#include <cuda_runtime.h>
#include <cuda_bf16.h>
#include <stdint.h>

// Problem constants
#define NN 50000
#define NE 800000
#define NF 256
#define NH 128
#define NC 64

// ============================ device scratch ============================
__device__ int    g_edges[2 * NE];      // [0..NE) = src, [NE..2NE) = dst
__device__ int    g_counts[NN];
__device__ int    g_off[NN + 1];
__device__ int    g_cursor[NN];
__device__ int    g_csr[NE];            // src per incoming edge (grouped by dst)
__device__ float  g_csrw[NE];           // dinv[src] per entry
__device__ float  g_dinv[NN];
__device__ float  g_H1[NN * NH];
__device__ float  g_A1[NN * NH];        // post-dropout activation (fp32)
__device__ float  g_H2[NN * NC];
__device__ float  g_Bt1[NH * NF];       // W1^T, tf32-rounded fp32, [N][K] K-contig
__device__ float  g_Bt2[NC * NH];       // W2^T, tf32-rounded fp32

// ============================ CSR build (R12-exact) ============================
__global__ void zero_counts_kernel() {
    int tid = blockIdx.x * blockDim.x + threadIdx.x;
    if (tid < NN) g_counts[tid] = 0;
}

__global__ void convert_hist_kernel(const void* ein) {
    const unsigned int* e32 = (const unsigned int*)ein;
    bool is64 = true;
#pragma unroll
    for (int i = 0; i < 8; i++) {
        if (e32[2 * i + 1] != 0u) { is64 = false; break; }
    }
    int i = blockIdx.x * blockDim.x + threadIdx.x;
    if (i >= 2 * NE) return;
    int v = is64 ? (int)((const long long*)ein)[i] : ((const int*)ein)[i];
    g_edges[i] = v;
    if (i >= NE) atomicAdd(&g_counts[v], 1);
}

__global__ void scan_kernel() {
    __shared__ int sh[1024];
    const int t = threadIdx.x;
    const int per = (NN + 1023) >> 10;
    int lo = t * per;
    int hi = lo + per; if (hi > NN) hi = NN;
    if (lo > NN) lo = NN;
    int s = 0;
    for (int i = lo; i < hi; i++) s += g_counts[i];
    sh[t] = s;
    __syncthreads();
    for (int off = 1; off < 1024; off <<= 1) {
        int v = (t >= off) ? sh[t - off] : 0;
        __syncthreads();
        sh[t] += v;
        __syncthreads();
    }
    int base = (t > 0) ? sh[t - 1] : 0;
    for (int i = lo; i < hi; i++) {
        g_off[i] = base;
        g_cursor[i] = base;
        base += g_counts[i];
        g_dinv[i] = rsqrtf((float)(g_counts[i] + 1));
    }
    if (t == 1023) g_off[NN] = sh[1023];
}

__global__ void fill_kernel() {
    int e = blockIdx.x * blockDim.x + threadIdx.x;
    if (e >= NE) return;
    int d = g_edges[NE + e];
    int s = g_edges[e];
    int p = atomicAdd(&g_cursor[d], 1);
    g_csr[p] = s;
    g_csrw[p] = g_dinv[s];
}

// ============================ tf32 helpers ============================
__device__ __forceinline__ uint32_t f2tf32(float f) {
    uint32_t r;
    asm("cvt.rna.tf32.f32 %0, %1;" : "=r"(r) : "f"(f));
    return r;
}

// weight prep: W[K,N] -> Bt[N][K], tf32-rounded, both layers in one launch
__global__ void wprep_kernel(const float* __restrict__ W1, const float* __restrict__ W2) {
    int i = blockIdx.x * blockDim.x + threadIdx.x;
    if (i < NH * NF) {
        int n = i / NF, k = i % NF;
        g_Bt1[i] = __uint_as_float(f2tf32(W1[k * NH + n]));
    } else if (i < NH * NF + NC * NH) {
        int t = i - NH * NF;
        int n = t / NH, k = t % NH;
        g_Bt2[t] = __uint_as_float(f2tf32(W2[k * NC + n]));
    }
}

// ============================ single-pass tf32 GEMM ============================
// C[M,BN] = A[M,K] @ W[K,BN]; A fp32 (cvt to tf32 on smem store), Bt pre-rounded [BN][K].
// mma.sync.m16n8k8 tf32. BM=128, BK=32, 256 threads (8 warps).
__device__ __forceinline__ void mma_tf32(float* c,
                                         uint32_t a0, uint32_t a1, uint32_t a2, uint32_t a3,
                                         uint32_t b0, uint32_t b1) {
    asm volatile(
        "mma.sync.aligned.m16n8k8.row.col.f32.tf32.tf32.f32 "
        "{%0,%1,%2,%3}, {%4,%5,%6,%7}, {%8,%9}, {%0,%1,%2,%3};"
        : "+f"(c[0]), "+f"(c[1]), "+f"(c[2]), "+f"(c[3])
        : "r"(a0), "r"(a1), "r"(a2), "r"(a3), "r"(b0), "r"(b1));
}

template <int BN, int K>
__global__ __launch_bounds__(256) void gemm_tf32_kernel(
    const float* __restrict__ A, const float* __restrict__ Bt,
    float* __restrict__ C, int M)
{
    constexpr int BM = 128, BK = 32;
    constexpr int LDA = 36;                       // 36 ≡ 4 (mod 32): frag loads conflict-free
    constexpr int WARPS_M = (BN == 128) ? 2 : 4;
    constexpr int WARPS_N = 8 / WARPS_M;
    constexpr int MT = BM / (WARPS_M * 16);       // 4 | 2
    constexpr int NT = BN / (WARPS_N * 8);        // 4 | 4

    __shared__ float As[BM * LDA];
    __shared__ float Bs[BN * LDA];

    const int tid = threadIdx.x;
    const int wid = tid >> 5;
    const int lane = tid & 31;
    const int g = lane >> 2;
    const int tig = lane & 3;
    const int warp_m = wid % WARPS_M;
    const int warp_n = wid / WARPS_M;
    const int wm0 = warp_m * MT * 16;
    const int wn0 = warp_n * NT * 8;
    const int row0 = blockIdx.x * BM;

    float acc[MT][NT][4];
#pragma unroll
    for (int mt = 0; mt < MT; mt++)
#pragma unroll
        for (int nt = 0; nt < NT; nt++)
#pragma unroll
            for (int i = 0; i < 4; i++) acc[mt][nt][i] = 0.f;

    for (int kc = 0; kc < K; kc += BK) {
        __syncthreads();
        // A tile: BM x BK fp32 -> tf32 into smem (4 float4 per thread)
#pragma unroll
        for (int l = 0; l < (BM * BK) / (256 * 4); l++) {
            int idx = l * 256 + tid;
            int r = idx >> 3;
            int kq = (idx & 7) * 4;
            float4 f = make_float4(0.f, 0.f, 0.f, 0.f);
            if (row0 + r < M) f = *(const float4*)&A[(size_t)(row0 + r) * K + kc + kq];
            float4 t;
            t.x = __uint_as_float(f2tf32(f.x));
            t.y = __uint_as_float(f2tf32(f.y));
            t.z = __uint_as_float(f2tf32(f.z));
            t.w = __uint_as_float(f2tf32(f.w));
            *(float4*)&As[r * LDA + kq] = t;
        }
        // B tile: BN x BK (already tf32-rounded) -> smem
#pragma unroll
        for (int l = 0; l < (BN * BK) / (256 * 4); l++) {
            int idx = l * 256 + tid;
            int n = idx >> 3;
            int kq = (idx & 7) * 4;
            *(float4*)&Bs[n * LDA + kq] = *(const float4*)&Bt[(size_t)n * K + kc + kq];
        }
        __syncthreads();

#pragma unroll
        for (int kk = 0; kk < BK; kk += 8) {
            uint32_t af[MT][4], bf[NT][2];
#pragma unroll
            for (int mt = 0; mt < MT; mt++) {
                int r0 = wm0 + mt * 16 + g;
                af[mt][0] = *(const uint32_t*)&As[r0 * LDA + kk + tig];
                af[mt][1] = *(const uint32_t*)&As[(r0 + 8) * LDA + kk + tig];
                af[mt][2] = *(const uint32_t*)&As[r0 * LDA + kk + tig + 4];
                af[mt][3] = *(const uint32_t*)&As[(r0 + 8) * LDA + kk + tig + 4];
            }
#pragma unroll
            for (int nt = 0; nt < NT; nt++) {
                int n0 = wn0 + nt * 8 + g;
                bf[nt][0] = *(const uint32_t*)&Bs[n0 * LDA + kk + tig];
                bf[nt][1] = *(const uint32_t*)&Bs[n0 * LDA + kk + tig + 4];
            }
#pragma unroll
            for (int mt = 0; mt < MT; mt++)
#pragma unroll
                for (int nt = 0; nt < NT; nt++)
                    mma_tf32(acc[mt][nt], af[mt][0], af[mt][1], af[mt][2], af[mt][3],
                             bf[nt][0], bf[nt][1]);
        }
    }

#pragma unroll
    for (int mt = 0; mt < MT; mt++) {
        int r0 = row0 + wm0 + mt * 16 + g;
#pragma unroll
        for (int nt = 0; nt < NT; nt++) {
            int c0 = wn0 + nt * 8 + tig * 2;
            if (r0 < M)
                *(float2*)&C[(size_t)r0 * BN + c0] = make_float2(acc[mt][nt][0], acc[mt][nt][1]);
            if (r0 + 8 < M)
                *(float2*)&C[(size_t)(r0 + 8) * BN + c0] = make_float2(acc[mt][nt][2], acc[mt][nt][3]);
        }
    }
}

// ============================ Threefry + dropout ============================
__device__ __forceinline__ unsigned int rotl32(unsigned int x, int d) {
    return (x << d) | (x >> (32 - d));
}
__device__ __forceinline__ void threefry2x32(unsigned int k0, unsigned int k1,
                                             unsigned int x0, unsigned int x1,
                                             unsigned int& o0, unsigned int& o1) {
    unsigned int ks0 = k0, ks1 = k1, ks2 = k0 ^ k1 ^ 0x1BD11BDAu;
    x0 += ks0; x1 += ks1;
#define TF_R4(a, b, c, d)                                 \
    x0 += x1; x1 = rotl32(x1, a); x1 ^= x0;               \
    x0 += x1; x1 = rotl32(x1, b); x1 ^= x0;               \
    x0 += x1; x1 = rotl32(x1, c); x1 ^= x0;               \
    x0 += x1; x1 = rotl32(x1, d); x1 ^= x0;
    TF_R4(13, 15, 26, 6);  x0 += ks1; x1 += ks2 + 1u;
    TF_R4(17, 29, 16, 24); x0 += ks2; x1 += ks0 + 2u;
    TF_R4(13, 15, 26, 6);  x0 += ks0; x1 += ks1 + 3u;
    TF_R4(17, 29, 16, 24); x0 += ks1; x1 += ks2 + 4u;
    TF_R4(13, 15, 26, 6);  x0 += ks2; x1 += ks0 + 5u;
#undef TF_R4
    o0 = x0; o1 = x1;
}
// keep[j]: bit31(b1^b2)==0 for threefry2x32((0,42),(0,j)) — JAX partitionable 32-bit.
__device__ __forceinline__ bool drop_keep(unsigned int j) {
    unsigned int o0, o1;
    threefry2x32(0u, 42u, 0u, j, o0, o1);
    return ((o0 ^ o1) & 0x80000000u) == 0u;
}

// ============================ gathers (R12-exact shapes) ============================
// Layer 1: aggregate fp32 H1, + b1, relu, dropout -> fp32 A1.
__global__ void gather128_fused_kernel(const float* __restrict__ H,
                                       const float* __restrict__ b,
                                       float* __restrict__ out) {
    int gwarp = (blockIdx.x * blockDim.x + threadIdx.x) >> 5;
    int lane = threadIdx.x & 31;
    int nwarp = (gridDim.x * blockDim.x) >> 5;
    const float4* __restrict__ H4 = (const float4*)H;
    float4 bv = ((const float4*)b)[lane];
    for (int d = gwarp; d < NN; d += nwarp) {
        float dd = g_dinv[d];
        float4 hv = H4[(size_t)d * 32 + lane];
        float4 acc = make_float4(dd * hv.x, dd * hv.y, dd * hv.z, dd * hv.w);
        int i = g_off[d], e1 = g_off[d + 1];
        for (; i + 4 <= e1; i += 4) {
            int a0 = g_csr[i], a1 = g_csr[i + 1], a2 = g_csr[i + 2], a3 = g_csr[i + 3];
            float w0 = g_csrw[i], w1 = g_csrw[i + 1], w2 = g_csrw[i + 2], w3 = g_csrw[i + 3];
            float4 v0 = H4[(size_t)a0 * 32 + lane];
            float4 v1 = H4[(size_t)a1 * 32 + lane];
            float4 v2 = H4[(size_t)a2 * 32 + lane];
            float4 v3 = H4[(size_t)a3 * 32 + lane];
            acc.x += w0 * v0.x + w1 * v1.x + w2 * v2.x + w3 * v3.x;
            acc.y += w0 * v0.y + w1 * v1.y + w2 * v2.y + w3 * v3.y;
            acc.z += w0 * v0.z + w1 * v1.z + w2 * v2.z + w3 * v3.z;
            acc.w += w0 * v0.w + w1 * v1.w + w2 * v2.w + w3 * v3.w;
        }
        for (; i < e1; i++) {
            int s = g_csr[i];
            float w = g_csrw[i];
            float4 v = H4[(size_t)s * 32 + lane];
            acc.x += w * v.x; acc.y += w * v.y; acc.z += w * v.z; acc.w += w * v.w;
        }
        unsigned int j = (unsigned int)d * 128u + (unsigned int)lane * 4u;
        acc.x = fmaxf(fmaf(dd, acc.x, bv.x), 0.f);
        acc.y = fmaxf(fmaf(dd, acc.y, bv.y), 0.f);
        acc.z = fmaxf(fmaf(dd, acc.z, bv.z), 0.f);
        acc.w = fmaxf(fmaf(dd, acc.w, bv.w), 0.f);
        acc.x = drop_keep(j + 0u) ? 2.f * acc.x : 0.f;
        acc.y = drop_keep(j + 1u) ? 2.f * acc.y : 0.f;
        acc.z = drop_keep(j + 2u) ? 2.f * acc.z : 0.f;
        acc.w = drop_keep(j + 3u) ? 2.f * acc.w : 0.f;
        ((float4*)out)[(size_t)d * 32 + lane] = acc;
    }
}

// Layer 2: aggregate fp32 H2 + b2 -> fp32 d_out.
__global__ void gather64_kernel(const float* __restrict__ H, const float* __restrict__ b,
                                float* __restrict__ out) {
    int gwarp = (blockIdx.x * blockDim.x + threadIdx.x) >> 5;
    int lane = threadIdx.x & 31;
    int nwarp = (gridDim.x * blockDim.x) >> 5;
    const float2* __restrict__ H2 = (const float2*)H;
    float2 bv = ((const float2*)b)[lane];
    for (int d = gwarp; d < NN; d += nwarp) {
        float dd = g_dinv[d];
        float2 hv = H2[(size_t)d * 32 + lane];
        float2 acc = make_float2(dd * hv.x, dd * hv.y);
        int i = g_off[d], e1 = g_off[d + 1];
        for (; i + 4 <= e1; i += 4) {
            int a0 = g_csr[i], a1 = g_csr[i + 1], a2 = g_csr[i + 2], a3 = g_csr[i + 3];
            float w0 = g_csrw[i], w1 = g_csrw[i + 1], w2 = g_csrw[i + 2], w3 = g_csrw[i + 3];
            float2 v0 = H2[(size_t)a0 * 32 + lane];
            float2 v1 = H2[(size_t)a1 * 32 + lane];
            float2 v2 = H2[(size_t)a2 * 32 + lane];
            float2 v3 = H2[(size_t)a3 * 32 + lane];
            acc.x += w0 * v0.x + w1 * v1.x + w2 * v2.x + w3 * v3.x;
            acc.y += w0 * v0.y + w1 * v1.y + w2 * v2.y + w3 * v3.y;
        }
        for (; i < e1; i++) {
            int s = g_csr[i];
            float w = g_csrw[i];
            float2 v = H2[(size_t)s * 32 + lane];
            acc.x += w * v.x; acc.y += w * v.y;
        }
        acc.x = fmaf(dd, acc.x, bv.x);
        acc.y = fmaf(dd, acc.y, bv.y);
        ((float2*)out)[(size_t)d * 32 + lane] = acc;
    }
}

// ============================ launch ============================
extern "C" void kernel_launch(void* const* d_in, const int* in_sizes, int n_in,
                              void* d_out, int out_size) {
    static cudaStream_t s2 = 0;
    static cudaEvent_t ev_fork = 0, ev_join = 0;
    if (!s2) {
        cudaStreamCreateWithFlags(&s2, cudaStreamNonBlocking);
        cudaEventCreateWithFlags(&ev_fork, cudaEventDisableTiming);
        cudaEventCreateWithFlags(&ev_join, cudaEventDisableTiming);
    }

    const float* x  = 0; const void* ei = 0;
    const float* W1 = 0; const float* b1 = 0;
    const float* W2 = 0; const float* b2 = 0;
    for (int i = 0; i < n_in; i++) {
        switch (in_sizes[i]) {
            case NN * NF:  x  = (const float*)d_in[i]; break;
            case 2 * NE:   ei = d_in[i];               break;
            case NF * NH:  W1 = (const float*)d_in[i]; break;
            case NH:       b1 = (const float*)d_in[i]; break;
            case NH * NC:  W2 = (const float*)d_in[i]; break;
            case NC:       b2 = (const float*)d_in[i]; break;
        }
    }
    float* out = (float*)d_out;

    float* H1; cudaGetSymbolAddress((void**)&H1, g_H1);
    float* A1; cudaGetSymbolAddress((void**)&A1, g_A1);
    float* H2; cudaGetSymbolAddress((void**)&H2, g_H2);
    float* Bt1; cudaGetSymbolAddress((void**)&Bt1, g_Bt1);
    float* Bt2; cudaGetSymbolAddress((void**)&Bt2, g_Bt2);

    // Fork: CSR build on s2; weight prep + GEMM1 on main.
    cudaEventRecord(ev_fork, 0);
    cudaStreamWaitEvent(s2, ev_fork, 0);

    zero_counts_kernel<<<(NN + 255) / 256, 256, 0, s2>>>();
    convert_hist_kernel<<<(2 * NE + 255) / 256, 256, 0, s2>>>(ei);
    scan_kernel<<<1, 1024, 0, s2>>>();
    fill_kernel<<<(NE + 255) / 256, 256, 0, s2>>>();
    cudaEventRecord(ev_join, s2);

    wprep_kernel<<<(NH * NF + NC * NH + 255) / 256, 256>>>(W1, W2);
    gemm_tf32_kernel<NH, NF><<<(NN + 127) / 128, 256>>>(x, Bt1, H1, NN);

    cudaStreamWaitEvent(0, ev_join, 0);

    gather128_fused_kernel<<<2048, 256>>>(H1, b1, A1);
    gemm_tf32_kernel<NC, NH><<<(NN + 127) / 128, 256>>>(A1, Bt2, H2, NN);
    gather64_kernel<<<1024, 256>>>(H2, b2, out);
}

// round 17
// speedup vs baseline: 1.2217x; 1.1018x over previous
#include <cuda_runtime.h>
#include <cuda_bf16.h>
#include <stdint.h>

// Problem constants
#define NN 50000
#define NE 800000
#define NF 256
#define NH 128
#define NC 64
#define NHALF 25088   // 196 * 128; first node-half for the tail pipeline

// ============================ device scratch ============================
__device__ int    g_edges[2 * NE];      // [0..NE) = src, [NE..2NE) = dst
__device__ int    g_counts[NN];
__device__ int    g_off[NN + 1];
__device__ int    g_cursor[NN];
__device__ int    g_csr[NE];
__device__ float  g_csrw[NE];
__device__ float  g_dinv[NN];
__device__ float  g_H1[NN * NH];
__device__ __nv_bfloat16 g_A1h[NN * NH], g_A1l[NN * NH];    // post-dropout activation, split
__device__ float  g_H2[NN * NC];
__device__ __nv_bfloat16 g_B1h[NH * NF], g_B1l[NH * NF];    // W1^T split: [N][K]
__device__ __nv_bfloat16 g_B2h[NC * NH], g_B2l[NC * NH];    // W2^T split

// ============================ CSR build (R12-exact) ============================
__global__ void zero_counts_kernel() {
    int tid = blockIdx.x * blockDim.x + threadIdx.x;
    if (tid < NN) g_counts[tid] = 0;
}

__global__ void convert_hist_kernel(const void* ein) {
    const unsigned int* e32 = (const unsigned int*)ein;
    bool is64 = true;
#pragma unroll
    for (int i = 0; i < 8; i++) {
        if (e32[2 * i + 1] != 0u) { is64 = false; break; }
    }
    int i = blockIdx.x * blockDim.x + threadIdx.x;
    if (i >= 2 * NE) return;
    int v = is64 ? (int)((const long long*)ein)[i] : ((const int*)ein)[i];
    g_edges[i] = v;
    if (i >= NE) atomicAdd(&g_counts[v], 1);
}

__global__ void scan_kernel() {
    __shared__ int sh[1024];
    const int t = threadIdx.x;
    const int per = (NN + 1023) >> 10;
    int lo = t * per;
    int hi = lo + per; if (hi > NN) hi = NN;
    if (lo > NN) lo = NN;
    int s = 0;
    for (int i = lo; i < hi; i++) s += g_counts[i];
    sh[t] = s;
    __syncthreads();
    for (int off = 1; off < 1024; off <<= 1) {
        int v = (t >= off) ? sh[t - off] : 0;
        __syncthreads();
        sh[t] += v;
        __syncthreads();
    }
    int base = (t > 0) ? sh[t - 1] : 0;
    for (int i = lo; i < hi; i++) {
        g_off[i] = base;
        g_cursor[i] = base;
        base += g_counts[i];
        g_dinv[i] = rsqrtf((float)(g_counts[i] + 1));
    }
    if (t == 1023) g_off[NN] = sh[1023];
}

__global__ void fill_kernel() {
    int e = blockIdx.x * blockDim.x + threadIdx.x;
    if (e >= NE) return;
    int d = g_edges[NE + e];
    int s = g_edges[e];
    int p = atomicAdd(&g_cursor[d], 1);
    g_csr[p] = s;
    g_csrw[p] = g_dinv[s];
}

// ============================ weight prep (R12-exact) ============================
template <int K, int N>
__global__ void wprep_kernel(const float* __restrict__ W,
                             __nv_bfloat16* __restrict__ bh, __nv_bfloat16* __restrict__ bl) {
    int i = blockIdx.x * blockDim.x + threadIdx.x;
    if (i >= N * K) return;
    int n = i / K, k = i % K;
    float f = W[k * N + n];
    __nv_bfloat16 h = __float2bfloat16_rn(f);
    float lo = f - __bfloat162float(h);
    bh[i] = h;
    bl[i] = __float2bfloat16_rn(lo);
}

// ============================ mma.sync bf16x3 GEMM ============================
__device__ __forceinline__ void mma_bf16(float* c,
                                         uint32_t a0, uint32_t a1, uint32_t a2, uint32_t a3,
                                         uint32_t b0, uint32_t b1) {
    asm volatile(
        "mma.sync.aligned.m16n8k16.row.col.f32.bf16.bf16.f32 "
        "{%0,%1,%2,%3}, {%4,%5,%6,%7}, {%8,%9}, {%0,%1,%2,%3};"
        : "+f"(c[0]), "+f"(c[1]), "+f"(c[2]), "+f"(c[3])
        : "r"(a0), "r"(a1), "r"(a2), "r"(a3), "r"(b0), "r"(b1));
}

// gemm1: C[M,BN] = A[M,K] @ W[K,BN], fp32 in/out, bf16x3 internally.
template <int BN, int K>
__global__ __launch_bounds__(256) void gemm_mma_kernel(
    const float* __restrict__ A,
    const __nv_bfloat16* __restrict__ Bh, const __nv_bfloat16* __restrict__ Bl,
    float* __restrict__ C, int M)
{
    constexpr int BM = 128, BK = 32;
    constexpr int LDA = 40;
    constexpr int WARPS_M = (BN == 128) ? 2 : 4;
    constexpr int WARPS_N = 8 / WARPS_M;
    constexpr int MT = BM / (WARPS_M * 16);
    constexpr int NT = BN / (WARPS_N * 8);

    __shared__ unsigned short Ah[BM * LDA], Al[BM * LDA];
    __shared__ unsigned short Bsh[BN * LDA], Bsl[BN * LDA];

    const int tid = threadIdx.x;
    const int wid = tid >> 5;
    const int lane = tid & 31;
    const int g = lane >> 2;
    const int tig = lane & 3;
    const int warp_m = wid % WARPS_M;
    const int warp_n = wid / WARPS_M;
    const int wm0 = warp_m * MT * 16;
    const int wn0 = warp_n * NT * 8;
    const int row0 = blockIdx.x * BM;

    float acc[MT][NT][4];
#pragma unroll
    for (int mt = 0; mt < MT; mt++)
#pragma unroll
        for (int nt = 0; nt < NT; nt++)
#pragma unroll
            for (int i = 0; i < 4; i++) acc[mt][nt][i] = 0.f;

    for (int kc = 0; kc < K; kc += BK) {
        __syncthreads();
#pragma unroll
        for (int l = 0; l < (BM * BK) / (256 * 4); l++) {
            int idx = l * 256 + tid;
            int r = idx >> 3;
            int kq = (idx & 7) * 4;
            float4 f = make_float4(0.f, 0.f, 0.f, 0.f);
            if (row0 + r < M) f = *(const float4*)&A[(size_t)(row0 + r) * K + kc + kq];
            __nv_bfloat162 h0 = __float22bfloat162_rn(make_float2(f.x, f.y));
            __nv_bfloat162 h1 = __float22bfloat162_rn(make_float2(f.z, f.w));
            float2 hb0 = __bfloat1622float2(h0);
            float2 hb1 = __bfloat1622float2(h1);
            __nv_bfloat162 l0 = __float22bfloat162_rn(make_float2(f.x - hb0.x, f.y - hb0.y));
            __nv_bfloat162 l1 = __float22bfloat162_rn(make_float2(f.z - hb1.x, f.w - hb1.y));
            *(uint32_t*)&Ah[r * LDA + kq]     = *(uint32_t*)&h0;
            *(uint32_t*)&Ah[r * LDA + kq + 2] = *(uint32_t*)&h1;
            *(uint32_t*)&Al[r * LDA + kq]     = *(uint32_t*)&l0;
            *(uint32_t*)&Al[r * LDA + kq + 2] = *(uint32_t*)&l1;
        }
#pragma unroll
        for (int l = 0; l < (BN * BK) / (256 * 8); l++) {
            int idx = l * 256 + tid;
            int n = idx >> 2;
            int kq = (idx & 3) * 8;
            *(uint4*)&Bsh[n * LDA + kq] = *(const uint4*)&Bh[(size_t)n * K + kc + kq];
            *(uint4*)&Bsl[n * LDA + kq] = *(const uint4*)&Bl[(size_t)n * K + kc + kq];
        }
        __syncthreads();

#pragma unroll
        for (int kk = 0; kk < BK; kk += 16) {
            uint32_t af[MT][4], bfh[NT][2], bfl[NT][2];
#pragma unroll
            for (int mt = 0; mt < MT; mt++) {
                int r0 = wm0 + mt * 16 + g;
                af[mt][0] = *(const uint32_t*)&Ah[r0 * LDA + kk + tig * 2];
                af[mt][1] = *(const uint32_t*)&Ah[(r0 + 8) * LDA + kk + tig * 2];
                af[mt][2] = *(const uint32_t*)&Ah[r0 * LDA + kk + 8 + tig * 2];
                af[mt][3] = *(const uint32_t*)&Ah[(r0 + 8) * LDA + kk + 8 + tig * 2];
            }
#pragma unroll
            for (int nt = 0; nt < NT; nt++) {
                int n0 = wn0 + nt * 8 + g;
                bfh[nt][0] = *(const uint32_t*)&Bsh[n0 * LDA + kk + tig * 2];
                bfh[nt][1] = *(const uint32_t*)&Bsh[n0 * LDA + kk + 8 + tig * 2];
                bfl[nt][0] = *(const uint32_t*)&Bsl[n0 * LDA + kk + tig * 2];
                bfl[nt][1] = *(const uint32_t*)&Bsl[n0 * LDA + kk + 8 + tig * 2];
            }
#pragma unroll
            for (int mt = 0; mt < MT; mt++)
#pragma unroll
                for (int nt = 0; nt < NT; nt++) {
                    mma_bf16(acc[mt][nt], af[mt][0], af[mt][1], af[mt][2], af[mt][3],
                             bfh[nt][0], bfh[nt][1]);
                    mma_bf16(acc[mt][nt], af[mt][0], af[mt][1], af[mt][2], af[mt][3],
                             bfl[nt][0], bfl[nt][1]);
                }
#pragma unroll
            for (int mt = 0; mt < MT; mt++) {
                int r0 = wm0 + mt * 16 + g;
                af[mt][0] = *(const uint32_t*)&Al[r0 * LDA + kk + tig * 2];
                af[mt][1] = *(const uint32_t*)&Al[(r0 + 8) * LDA + kk + tig * 2];
                af[mt][2] = *(const uint32_t*)&Al[r0 * LDA + kk + 8 + tig * 2];
                af[mt][3] = *(const uint32_t*)&Al[(r0 + 8) * LDA + kk + 8 + tig * 2];
            }
#pragma unroll
            for (int mt = 0; mt < MT; mt++)
#pragma unroll
                for (int nt = 0; nt < NT; nt++)
                    mma_bf16(acc[mt][nt], af[mt][0], af[mt][1], af[mt][2], af[mt][3],
                             bfh[nt][0], bfh[nt][1]);
        }
    }

#pragma unroll
    for (int mt = 0; mt < MT; mt++) {
        int r0 = row0 + wm0 + mt * 16 + g;
#pragma unroll
        for (int nt = 0; nt < NT; nt++) {
            int c0 = wn0 + nt * 8 + tig * 2;
            if (r0 < M)
                *(float2*)&C[(size_t)r0 * BN + c0] = make_float2(acc[mt][nt][0], acc[mt][nt][1]);
            if (r0 + 8 < M)
                *(float2*)&C[(size_t)(r0 + 8) * BN + c0] = make_float2(acc[mt][nt][2], acc[mt][nt][3]);
        }
    }
}

// gemm2: pre-split bf16 A (from gather128), fp32 out. Rows [0, M) of given pointers.
__global__ __launch_bounds__(256) void gemm2_mma_kernel(
    const __nv_bfloat16* __restrict__ A1h, const __nv_bfloat16* __restrict__ A1l,
    const __nv_bfloat16* __restrict__ Bh, const __nv_bfloat16* __restrict__ Bl,
    float* __restrict__ C, int M)
{
    constexpr int BN = 64, K = 128;
    constexpr int BM = 128, BK = 32;
    constexpr int LDA = 40;
    constexpr int WARPS_M = 4, WARPS_N = 2;
    constexpr int MT = BM / (WARPS_M * 16);   // 2
    constexpr int NT = BN / (WARPS_N * 8);    // 4

    __shared__ unsigned short Ah[BM * LDA], Al[BM * LDA];
    __shared__ unsigned short Bsh[BN * LDA], Bsl[BN * LDA];

    const int tid = threadIdx.x;
    const int wid = tid >> 5;
    const int lane = tid & 31;
    const int g = lane >> 2;
    const int tig = lane & 3;
    const int warp_m = wid % WARPS_M;
    const int warp_n = wid / WARPS_M;
    const int wm0 = warp_m * MT * 16;
    const int wn0 = warp_n * NT * 8;
    const int row0 = blockIdx.x * BM;

    float acc[MT][NT][4];
#pragma unroll
    for (int mt = 0; mt < MT; mt++)
#pragma unroll
        for (int nt = 0; nt < NT; nt++)
#pragma unroll
            for (int i = 0; i < 4; i++) acc[mt][nt][i] = 0.f;

    for (int kc = 0; kc < K; kc += BK) {
        __syncthreads();
#pragma unroll
        for (int l = 0; l < (BM * BK) / (256 * 8); l++) {
            int idx = l * 256 + tid;
            int r = idx >> 2;
            int kq = (idx & 3) * 8;
            uint4 vh = make_uint4(0u, 0u, 0u, 0u), vl = make_uint4(0u, 0u, 0u, 0u);
            if (row0 + r < M) {
                vh = *(const uint4*)&A1h[(size_t)(row0 + r) * K + kc + kq];
                vl = *(const uint4*)&A1l[(size_t)(row0 + r) * K + kc + kq];
            }
            *(uint4*)&Ah[r * LDA + kq] = vh;
            *(uint4*)&Al[r * LDA + kq] = vl;
        }
        {
            int n = tid >> 2;
            int kq = (tid & 3) * 8;
            *(uint4*)&Bsh[n * LDA + kq] = *(const uint4*)&Bh[(size_t)n * K + kc + kq];
            *(uint4*)&Bsl[n * LDA + kq] = *(const uint4*)&Bl[(size_t)n * K + kc + kq];
        }
        __syncthreads();

#pragma unroll
        for (int kk = 0; kk < BK; kk += 16) {
            uint32_t af[MT][4], bfh[NT][2], bfl[NT][2];
#pragma unroll
            for (int mt = 0; mt < MT; mt++) {
                int r0 = wm0 + mt * 16 + g;
                af[mt][0] = *(const uint32_t*)&Ah[r0 * LDA + kk + tig * 2];
                af[mt][1] = *(const uint32_t*)&Ah[(r0 + 8) * LDA + kk + tig * 2];
                af[mt][2] = *(const uint32_t*)&Ah[r0 * LDA + kk + 8 + tig * 2];
                af[mt][3] = *(const uint32_t*)&Ah[(r0 + 8) * LDA + kk + 8 + tig * 2];
            }
#pragma unroll
            for (int nt = 0; nt < NT; nt++) {
                int n0 = wn0 + nt * 8 + g;
                bfh[nt][0] = *(const uint32_t*)&Bsh[n0 * LDA + kk + tig * 2];
                bfh[nt][1] = *(const uint32_t*)&Bsh[n0 * LDA + kk + 8 + tig * 2];
                bfl[nt][0] = *(const uint32_t*)&Bsl[n0 * LDA + kk + tig * 2];
                bfl[nt][1] = *(const uint32_t*)&Bsl[n0 * LDA + kk + 8 + tig * 2];
            }
#pragma unroll
            for (int mt = 0; mt < MT; mt++)
#pragma unroll
                for (int nt = 0; nt < NT; nt++) {
                    mma_bf16(acc[mt][nt], af[mt][0], af[mt][1], af[mt][2], af[mt][3],
                             bfh[nt][0], bfh[nt][1]);
                    mma_bf16(acc[mt][nt], af[mt][0], af[mt][1], af[mt][2], af[mt][3],
                             bfl[nt][0], bfl[nt][1]);
                }
#pragma unroll
            for (int mt = 0; mt < MT; mt++) {
                int r0 = wm0 + mt * 16 + g;
                af[mt][0] = *(const uint32_t*)&Al[r0 * LDA + kk + tig * 2];
                af[mt][1] = *(const uint32_t*)&Al[(r0 + 8) * LDA + kk + tig * 2];
                af[mt][2] = *(const uint32_t*)&Al[r0 * LDA + kk + 8 + tig * 2];
                af[mt][3] = *(const uint32_t*)&Al[(r0 + 8) * LDA + kk + 8 + tig * 2];
            }
#pragma unroll
            for (int mt = 0; mt < MT; mt++)
#pragma unroll
                for (int nt = 0; nt < NT; nt++)
                    mma_bf16(acc[mt][nt], af[mt][0], af[mt][1], af[mt][2], af[mt][3],
                             bfh[nt][0], bfh[nt][1]);
        }
    }

#pragma unroll
    for (int mt = 0; mt < MT; mt++) {
        int r0 = row0 + wm0 + mt * 16 + g;
#pragma unroll
        for (int nt = 0; nt < NT; nt++) {
            int c0 = wn0 + nt * 8 + tig * 2;
            if (r0 < M)
                *(float2*)&C[(size_t)r0 * BN + c0] = make_float2(acc[mt][nt][0], acc[mt][nt][1]);
            if (r0 + 8 < M)
                *(float2*)&C[(size_t)(r0 + 8) * BN + c0] = make_float2(acc[mt][nt][2], acc[mt][nt][3]);
        }
    }
}

// ============================ Threefry + dropout ============================
__device__ __forceinline__ unsigned int rotl32(unsigned int x, int d) {
    return (x << d) | (x >> (32 - d));
}
__device__ __forceinline__ void threefry2x32(unsigned int k0, unsigned int k1,
                                             unsigned int x0, unsigned int x1,
                                             unsigned int& o0, unsigned int& o1) {
    unsigned int ks0 = k0, ks1 = k1, ks2 = k0 ^ k1 ^ 0x1BD11BDAu;
    x0 += ks0; x1 += ks1;
#define TF_R4(a, b, c, d)                                 \
    x0 += x1; x1 = rotl32(x1, a); x1 ^= x0;               \
    x0 += x1; x1 = rotl32(x1, b); x1 ^= x0;               \
    x0 += x1; x1 = rotl32(x1, c); x1 ^= x0;               \
    x0 += x1; x1 = rotl32(x1, d); x1 ^= x0;
    TF_R4(13, 15, 26, 6);  x0 += ks1; x1 += ks2 + 1u;
    TF_R4(17, 29, 16, 24); x0 += ks2; x1 += ks0 + 2u;
    TF_R4(13, 15, 26, 6);  x0 += ks0; x1 += ks1 + 3u;
    TF_R4(17, 29, 16, 24); x0 += ks1; x1 += ks2 + 4u;
    TF_R4(13, 15, 26, 6);  x0 += ks2; x1 += ks0 + 5u;
#undef TF_R4
    o0 = x0; o1 = x1;
}
// keep[j]: bit31(b1^b2)==0 for threefry2x32((0,42),(0,j)) — JAX partitionable 32-bit.
__device__ __forceinline__ bool drop_keep(unsigned int j) {
    unsigned int o0, o1;
    threefry2x32(0u, 42u, 0u, j, o0, o1);
    return ((o0 ^ o1) & 0x80000000u) == 0u;
}

// ============================ gathers (R12-exact shapes, + node range) ============================
// Layer 1 over [lo, hi): aggregate fp32 H1, + b1, relu, dropout; write split bf16 hi/lo.
__global__ void gather128_fused_kernel(const float* __restrict__ H,
                                       const float* __restrict__ b,
                                       int lo, int hi) {
    int gwarp = (blockIdx.x * blockDim.x + threadIdx.x) >> 5;
    int lane = threadIdx.x & 31;
    int nwarp = (gridDim.x * blockDim.x) >> 5;
    const float4* __restrict__ H4 = (const float4*)H;
    float4 bv = ((const float4*)b)[lane];
    for (int d = lo + gwarp; d < hi; d += nwarp) {
        float dd = g_dinv[d];
        float4 hv = H4[(size_t)d * 32 + lane];
        float4 acc = make_float4(dd * hv.x, dd * hv.y, dd * hv.z, dd * hv.w);
        int i = g_off[d], e1 = g_off[d + 1];
        for (; i + 4 <= e1; i += 4) {
            int a0 = g_csr[i], a1 = g_csr[i + 1], a2 = g_csr[i + 2], a3 = g_csr[i + 3];
            float w0 = g_csrw[i], w1 = g_csrw[i + 1], w2 = g_csrw[i + 2], w3 = g_csrw[i + 3];
            float4 v0 = H4[(size_t)a0 * 32 + lane];
            float4 v1 = H4[(size_t)a1 * 32 + lane];
            float4 v2 = H4[(size_t)a2 * 32 + lane];
            float4 v3 = H4[(size_t)a3 * 32 + lane];
            acc.x += w0 * v0.x + w1 * v1.x + w2 * v2.x + w3 * v3.x;
            acc.y += w0 * v0.y + w1 * v1.y + w2 * v2.y + w3 * v3.y;
            acc.z += w0 * v0.z + w1 * v1.z + w2 * v2.z + w3 * v3.z;
            acc.w += w0 * v0.w + w1 * v1.w + w2 * v2.w + w3 * v3.w;
        }
        for (; i < e1; i++) {
            int s = g_csr[i];
            float w = g_csrw[i];
            float4 v = H4[(size_t)s * 32 + lane];
            acc.x += w * v.x; acc.y += w * v.y; acc.z += w * v.z; acc.w += w * v.w;
        }
        unsigned int j = (unsigned int)d * 128u + (unsigned int)lane * 4u;
        acc.x = fmaxf(fmaf(dd, acc.x, bv.x), 0.f);
        acc.y = fmaxf(fmaf(dd, acc.y, bv.y), 0.f);
        acc.z = fmaxf(fmaf(dd, acc.z, bv.z), 0.f);
        acc.w = fmaxf(fmaf(dd, acc.w, bv.w), 0.f);
        acc.x = drop_keep(j + 0u) ? 2.f * acc.x : 0.f;
        acc.y = drop_keep(j + 1u) ? 2.f * acc.y : 0.f;
        acc.z = drop_keep(j + 2u) ? 2.f * acc.z : 0.f;
        acc.w = drop_keep(j + 3u) ? 2.f * acc.w : 0.f;
        __nv_bfloat162 h0 = __float22bfloat162_rn(make_float2(acc.x, acc.y));
        __nv_bfloat162 h1 = __float22bfloat162_rn(make_float2(acc.z, acc.w));
        float2 hb0 = __bfloat1622float2(h0);
        float2 hb1 = __bfloat1622float2(h1);
        __nv_bfloat162 l0 = __float22bfloat162_rn(make_float2(acc.x - hb0.x, acc.y - hb0.y));
        __nv_bfloat162 l1 = __float22bfloat162_rn(make_float2(acc.z - hb1.x, acc.w - hb1.y));
        uint2 hw = make_uint2(*(uint32_t*)&h0, *(uint32_t*)&h1);
        uint2 lw = make_uint2(*(uint32_t*)&l0, *(uint32_t*)&l1);
        *(uint2*)&g_A1h[(size_t)d * 128 + lane * 4] = hw;
        *(uint2*)&g_A1l[(size_t)d * 128 + lane * 4] = lw;
    }
}

// Layer 2: aggregate fp32 H2 + b2 -> fp32 d_out.
__global__ void gather64_kernel(const float* __restrict__ H, const float* __restrict__ b,
                                float* __restrict__ out) {
    int gwarp = (blockIdx.x * blockDim.x + threadIdx.x) >> 5;
    int lane = threadIdx.x & 31;
    int nwarp = (gridDim.x * blockDim.x) >> 5;
    const float2* __restrict__ H2 = (const float2*)H;
    float2 bv = ((const float2*)b)[lane];
    for (int d = gwarp; d < NN; d += nwarp) {
        float dd = g_dinv[d];
        float2 hv = H2[(size_t)d * 32 + lane];
        float2 acc = make_float2(dd * hv.x, dd * hv.y);
        int i = g_off[d], e1 = g_off[d + 1];
        for (; i + 4 <= e1; i += 4) {
            int a0 = g_csr[i], a1 = g_csr[i + 1], a2 = g_csr[i + 2], a3 = g_csr[i + 3];
            float w0 = g_csrw[i], w1 = g_csrw[i + 1], w2 = g_csrw[i + 2], w3 = g_csrw[i + 3];
            float2 v0 = H2[(size_t)a0 * 32 + lane];
            float2 v1 = H2[(size_t)a1 * 32 + lane];
            float2 v2 = H2[(size_t)a2 * 32 + lane];
            float2 v3 = H2[(size_t)a3 * 32 + lane];
            acc.x += w0 * v0.x + w1 * v1.x + w2 * v2.x + w3 * v3.x;
            acc.y += w0 * v0.y + w1 * v1.y + w2 * v2.y + w3 * v3.y;
        }
        for (; i < e1; i++) {
            int s = g_csr[i];
            float w = g_csrw[i];
            float2 v = H2[(size_t)s * 32 + lane];
            acc.x += w * v.x; acc.y += w * v.y;
        }
        acc.x = fmaf(dd, acc.x, bv.x);
        acc.y = fmaf(dd, acc.y, bv.y);
        ((float2*)out)[(size_t)d * 32 + lane] = acc;
    }
}

// ============================ launch ============================
extern "C" void kernel_launch(void* const* d_in, const int* in_sizes, int n_in,
                              void* d_out, int out_size) {
    static cudaStream_t s2 = 0;
    static cudaEvent_t ev_fork = 0, ev_join = 0, ev_g0 = 0, ev_gm = 0;
    if (!s2) {
        cudaStreamCreateWithFlags(&s2, cudaStreamNonBlocking);
        cudaEventCreateWithFlags(&ev_fork, cudaEventDisableTiming);
        cudaEventCreateWithFlags(&ev_join, cudaEventDisableTiming);
        cudaEventCreateWithFlags(&ev_g0, cudaEventDisableTiming);
        cudaEventCreateWithFlags(&ev_gm, cudaEventDisableTiming);
    }

    const float* x  = 0; const void* ei = 0;
    const float* W1 = 0; const float* b1 = 0;
    const float* W2 = 0; const float* b2 = 0;
    for (int i = 0; i < n_in; i++) {
        switch (in_sizes[i]) {
            case NN * NF:  x  = (const float*)d_in[i]; break;
            case 2 * NE:   ei = d_in[i];               break;
            case NF * NH:  W1 = (const float*)d_in[i]; break;
            case NH:       b1 = (const float*)d_in[i]; break;
            case NH * NC:  W2 = (const float*)d_in[i]; break;
            case NC:       b2 = (const float*)d_in[i]; break;
        }
    }
    float* out = (float*)d_out;

    float* H1; cudaGetSymbolAddress((void**)&H1, g_H1);
    float* H2; cudaGetSymbolAddress((void**)&H2, g_H2);
    __nv_bfloat16 *B1h, *B1l, *B2h, *B2l, *A1h, *A1l;
    cudaGetSymbolAddress((void**)&B1h, g_B1h);
    cudaGetSymbolAddress((void**)&B1l, g_B1l);
    cudaGetSymbolAddress((void**)&B2h, g_B2h);
    cudaGetSymbolAddress((void**)&B2l, g_B2l);
    cudaGetSymbolAddress((void**)&A1h, g_A1h);
    cudaGetSymbolAddress((void**)&A1l, g_A1l);

    // Fork: CSR build on s2; weight prep + GEMM1 on main.
    cudaEventRecord(ev_fork, 0);
    cudaStreamWaitEvent(s2, ev_fork, 0);

    zero_counts_kernel<<<(NN + 255) / 256, 256, 0, s2>>>();
    convert_hist_kernel<<<(2 * NE + 255) / 256, 256, 0, s2>>>(ei);
    scan_kernel<<<1, 1024, 0, s2>>>();
    fill_kernel<<<(NE + 255) / 256, 256, 0, s2>>>();
    cudaEventRecord(ev_join, s2);

    wprep_kernel<NF, NH><<<(NH * NF + 255) / 256, 256>>>(W1, B1h, B1l);
    wprep_kernel<NH, NC><<<(NC * NH + 255) / 256, 256>>>(W2, B2h, B2l);
    gemm_mma_kernel<NH, NF><<<(NN + 127) / 128, 256>>>(x, B1h, B1l, H1, NN);

    cudaStreamWaitEvent(0, ev_join, 0);

    // Tail pipeline: gather128(half0) -> { gemm2(half0) on s2 || gather128(half1) on main }
    //                -> gemm2(half1) on main -> join -> gather64.
    gather128_fused_kernel<<<2048, 256>>>(H1, b1, 0, NHALF);
    cudaEventRecord(ev_g0, 0);
    cudaStreamWaitEvent(s2, ev_g0, 0);
    gemm2_mma_kernel<<<NHALF / 128, 256, 0, s2>>>(A1h, A1l, B2h, B2l, H2, NHALF);
    cudaEventRecord(ev_gm, s2);

    gather128_fused_kernel<<<2048, 256>>>(H1, b1, NHALF, NN);
    gemm2_mma_kernel<<<(NN - NHALF + 127) / 128, 256>>>(
        A1h + (size_t)NHALF * NH, A1l + (size_t)NHALF * NH, B2h, B2l,
        H2 + (size_t)NHALF * NC, NN - NHALF);
    cudaStreamWaitEvent(0, ev_gm, 0);

    gather64_kernel<<<1024, 256>>>(H2, b2, out);
}